// round 6
// baseline (speedup 1.0000x reference)
#include <cuda_runtime.h>
#include <cuda_bf16.h>
#include <cstdint>

#define BATCH 2
#define C 128
#define H 96
#define W 96
#define HEADS 4
#define DHEAD 32
#define PAD 2
#define INNER 128
#define HW (H * W)
#define HP (H + 2 * PAD)
#define WP (W + 2 * PAD)
#define NTILES (HW / 128)   // 72

typedef unsigned long long u64;

// fp32 scratch
__device__ float g_q[(size_t)BATCH * HW * INNER];          // [b][p][inner]
__device__ float g_kpad[(size_t)BATCH * HP * WP * INNER];  // [b][yp][xp][inner]
__device__ float g_vpad[(size_t)BATCH * HP * WP * INNER];

// bf16 hi/lo operand images
__device__ __nv_bfloat16 g_xhi[(size_t)BATCH * HW * C];    // [b][p][c]
__device__ __nv_bfloat16 g_xlo[(size_t)BATCH * HW * C];
__device__ __nv_bfloat16 g_whi[4 * C * INNER];             // [mat][o][c]
__device__ __nv_bfloat16 g_wlo[4 * C * INNER];
__device__ __nv_bfloat16 g_ohi[(size_t)BATCH * HW * INNER];// [b][p][inner]
__device__ __nv_bfloat16 g_olo[(size_t)BATCH * HW * INNER];

#define FFMA2(d, a, b) \
    asm("fma.rn.f32x2 %0, %1, %2, %0;" : "+l"(d) : "l"(a), "l"(b))
#define PACK2(d, s) \
    asm("mov.b64 %0, {%1, %1};" : "=l"(d) : "f"(s))

__device__ __forceinline__ void cp16(uint32_t smem, const void* g) {
    asm volatile("cp.async.cg.shared.global [%0], [%1], 16;" :: "r"(smem), "l"(g));
}
#define CP_COMMIT() asm volatile("cp.async.commit_group;")
#define CP_WAIT(n)  asm volatile("cp.async.wait_group %0;" :: "n"(n))

__device__ __forceinline__ uint32_t smem_u32(const void* p) {
    uint32_t a;
    asm("{ .reg .u64 t; cvta.to.shared.u64 t, %1; cvt.u32.u64 %0, t; }"
        : "=r"(a) : "l"(p));
    return a;
}

// pack two f32 -> bf16x2 reg, v0 in low half (memory element 0)
#define PACK_BF16X2(res, v0, v1) \
    asm("cvt.rn.bf16x2.f32 %0, %1, %2;" : "=r"(res) : "f"(v1), "f"(v0))

#define LDM_X4(r, addr) \
    asm volatile("ldmatrix.sync.aligned.m8n8.x4.shared.b16 {%0,%1,%2,%3}, [%4];" \
        : "=r"((r)[0]), "=r"((r)[1]), "=r"((r)[2]), "=r"((r)[3]) : "r"(addr))

#define MMA16816(d, a, bp) \
    asm volatile("mma.sync.aligned.m16n8k16.row.col.f32.bf16.bf16.f32 " \
        "{%0,%1,%2,%3}, {%4,%5,%6,%7}, {%8,%9}, {%0,%1,%2,%3};" \
        : "+f"((d)[0]), "+f"((d)[1]), "+f"((d)[2]), "+f"((d)[3]) \
        : "r"((a)[0]), "r"((a)[1]), "r"((a)[2]), "r"((a)[3]), \
          "r"((bp)[0]), "r"((bp)[1]))

// smem tile: 128 rows x 128 bf16, row stride 272B (17*16 -> conflict-free)
#define TROW 272
#define TILE (128 * TROW)
#define GEMM_SMEM (4 * TILE)   // 139264

// ---------------------------------------------------------------------------
// Kernel A: split x (f32 [b][c][p]) -> g_xhi/g_xlo (bf16 [b][p][c])
// ---------------------------------------------------------------------------
__global__ __launch_bounds__(256) void xsplit_kernel(const float* __restrict__ x)
{
    __shared__ float t[32][33];
    const int p0 = blockIdx.x * 32, c0 = blockIdx.y * 32, b = blockIdx.z;
    const int tl = threadIdx.x & 31, th = threadIdx.x >> 5;
#pragma unroll
    for (int i = 0; i < 4; i++) {
        int c = th + i * 8;
        t[c][tl] = x[((size_t)b * C + c0 + c) * HW + p0 + tl];
    }
    __syncthreads();
#pragma unroll
    for (int i = 0; i < 4; i++) {
        int p = th + i * 8;
        float v = t[tl][p];
        __nv_bfloat16 hb = __float2bfloat16(v);
        float lov = v - __bfloat162float(hb);
        size_t off = ((size_t)b * HW + p0 + p) * C + c0 + tl;
        g_xhi[off] = hb;
        g_xlo[off] = __float2bfloat16(lov);
    }
}

// ---------------------------------------------------------------------------
// Kernel B: bake weights -> bf16 hi/lo [mat][o][c]
// ---------------------------------------------------------------------------
__global__ __launch_bounds__(256) void wbake_kernel(
    const float* __restrict__ wq, const float* __restrict__ wk,
    const float* __restrict__ wv, const float* __restrict__ wp)
{
    const int mat = blockIdx.y;
    const float* __restrict__ src =
        (mat == 0) ? wq : (mat == 1) ? wk : (mat == 2) ? wv : wp;
    int idx = blockIdx.x * 256 + threadIdx.x;
    float w = src[idx];
    __nv_bfloat16 hb = __float2bfloat16(w);
    float lov = w - __bfloat162float(hb);
    g_whi[mat * 16384 + idx] = hb;
    g_wlo[mat * 16384 + idx] = __float2bfloat16(lov);
}

// ---------------------------------------------------------------------------
// Shared HMMA mainloop (validated in R5)
// ---------------------------------------------------------------------------
__device__ __forceinline__ void mma_tiles(
    uint32_t Abase, uint32_t Bbase, int lane, int mwarp, int nwarp,
    float (*acc)[4])
{
    const uint32_t arow0 = Abase + (uint32_t)(mwarp + (lane & 15)) * TROW
                         + ((lane >> 4) & 1) * 16;
    const uint32_t brow0 = Bbase
                         + (uint32_t)(nwarp + ((lane >> 4) << 3) + (lane & 7)) * TROW
                         + ((lane >> 3) & 1) * 16;
#pragma unroll
    for (int k0 = 0; k0 < 8; k0++) {
        uint32_t a[4][4], bq[2][4];
#pragma unroll
        for (int mt = 0; mt < 4; mt++)
            LDM_X4(a[mt], arow0 + k0 * 32 + mt * (16 * TROW));
#pragma unroll
        for (int n2 = 0; n2 < 2; n2++)
            LDM_X4(bq[n2], brow0 + k0 * 32 + n2 * (16 * TROW));
#pragma unroll
        for (int mt = 0; mt < 4; mt++)
#pragma unroll
            for (int nt = 0; nt < 4; nt++)
                MMA16816(acc[mt * 4 + nt], a[mt], &bq[nt >> 1][(nt & 1) * 2]);
    }
}

__device__ __forceinline__ void stage_tile(
    uint32_t dst, const __nv_bfloat16* __restrict__ src, int tid)
{
    for (int i = tid; i < 2048; i += 256) {
        int r = i >> 4, ch = i & 15;
        cp16(dst + r * TROW + ch * 16, src + r * 128 + ch * 8);
    }
}

// ---------------------------------------------------------------------------
// Kernel 1: QKV. A = X (pixels) hi/lo, B = W hi/lo. D[p][o].
// ---------------------------------------------------------------------------
__global__ __launch_bounds__(256) void qkv_mma_kernel()
{
    extern __shared__ char sm[];
    const uint32_t smb = smem_u32(sm);
    const int tid = threadIdx.x, wid = tid >> 5, lane = tid & 31;
    const int pb = blockIdx.x, mat = blockIdx.y, b = blockIdx.z;
    const int p0 = pb * 128;

    const __nv_bfloat16* xh = g_xhi + ((size_t)b * HW + p0) * C;
    const __nv_bfloat16* xl = g_xlo + ((size_t)b * HW + p0) * C;
    const __nv_bfloat16* wh = g_whi + mat * 16384;
    const __nv_bfloat16* wl = g_wlo + mat * 16384;

    stage_tile(smb + 0 * TILE, xh, tid);
    stage_tile(smb + 2 * TILE, wh, tid);
    CP_COMMIT();
    stage_tile(smb + 1 * TILE, xl, tid);
    stage_tile(smb + 3 * TILE, wl, tid);
    CP_COMMIT();

    float acc[16][4];
#pragma unroll
    for (int i = 0; i < 16; i++)
#pragma unroll
        for (int j = 0; j < 4; j++) acc[i][j] = 0.f;

    const int mwarp = (wid >> 2) * 64, nwarp = (wid & 3) * 32;

    CP_WAIT(1);
    __syncthreads();
    mma_tiles(smb + 0 * TILE, smb + 2 * TILE, lane, mwarp, nwarp, acc);
    CP_WAIT(0);
    __syncthreads();
    mma_tiles(smb + 0 * TILE, smb + 3 * TILE, lane, mwarp, nwarp, acc);
    mma_tiles(smb + 1 * TILE, smb + 2 * TILE, lane, mwarp, nwarp, acc);

    const int gid = lane >> 2, tig = lane & 3;
#pragma unroll
    for (int mt = 0; mt < 4; mt++) {
#pragma unroll
        for (int half = 0; half < 2; half++) {
            int r = mwarp + mt * 16 + gid + half * 8;
            int p = p0 + r;
            float* dst;
            if (mat == 0) {
                dst = g_q + ((size_t)b * HW + p) * INNER;
            } else {
                int yy = p / W, xx = p - yy * W;
                float* base = (mat == 1) ? g_kpad : g_vpad;
                dst = base + (((size_t)b * HP + yy + PAD) * WP + (xx + PAD)) * INNER;
            }
#pragma unroll
            for (int nt = 0; nt < 4; nt++) {
                int o = nwarp + nt * 8 + 2 * tig;
                *(float2*)(dst + o) = make_float2(acc[mt * 4 + nt][half * 2],
                                                  acc[mt * 4 + nt][half * 2 + 1]);
            }
        }
    }
}

// ---------------------------------------------------------------------------
// Kernel 2: window attention. cp.async staging, 4 score accumulators,
// 2 blocks/SM.
// ---------------------------------------------------------------------------
#define TX 32
#define TY 8
#define PWT (TX + 4)
#define PHT (TY + 4)
#define NPIX (PWT * PHT)
#define DGS 433
#define ATTN_SMEM (2 * 8 * DGS * 16)

__global__ __launch_bounds__(256, 2) void attn_kernel()
{
    extern __shared__ float4 sm4[];
    float4* ks4 = sm4;
    float4* vs4 = sm4 + 8 * DGS;
    const uint32_t smbk = smem_u32(ks4);
    const uint32_t smbv = smem_u32(vs4);

    const int t  = threadIdx.x;
    const int x0 = blockIdx.x * TX;
    const int y0 = blockIdx.y * TY;
    const int h  = blockIdx.z & 3;
    const int b  = blockIdx.z >> 2;

    const float* __restrict__ kg =
        g_kpad + (((size_t)b * HP + y0) * WP + x0) * INNER + h * DHEAD;
    const float* __restrict__ vg =
        g_vpad + (((size_t)b * HP + y0) * WP + x0) * INNER + h * DHEAD;

#pragma unroll
    for (int i = t; i < NPIX * 8; i += 256) {
        int pp = i >> 3, dg = i & 7;
        int py = pp / PWT, px = pp - py * PWT;
        size_t goff = ((size_t)py * WP + px) * INNER + dg * 4;
        cp16(smbk + (uint32_t)(dg * DGS + pp) * 16, kg + goff);
        cp16(smbv + (uint32_t)(dg * DGS + pp) * 16, vg + goff);
    }
    CP_COMMIT();

    const int tx = t & 31, ty = t >> 5;
    const int p = (y0 + ty) * W + x0 + tx;
    u64 q2[16];
    const float* qp = g_q + ((size_t)b * HW + p) * INNER + h * DHEAD;
#pragma unroll
    for (int dg = 0; dg < 8; dg++) {
        ulonglong2 v = *(const ulonglong2*)(qp + dg * 4);
        q2[dg * 2] = v.x; q2[dg * 2 + 1] = v.y;
    }

    CP_WAIT(0);
    __syncthreads();

    const float scale = 0.17677669529663687f;
    float sc[25];
#pragma unroll
    for (int n = 0; n < 25; n++) {
        const int di = n / 5, dj = n - 5 * (n / 5);
        const int pix = (ty + di) * PWT + (tx + dj);
        u64 s4[4] = {0ull, 0ull, 0ull, 0ull};
#pragma unroll
        for (int dg = 0; dg < 4; dg++) {
            ulonglong2 kv0 = *(const ulonglong2*)&ks4[dg * DGS + pix];
            ulonglong2 kv1 = *(const ulonglong2*)&ks4[(dg + 4) * DGS + pix];
            FFMA2(s4[0], q2[dg * 2], kv0.x);
            FFMA2(s4[1], q2[dg * 2 + 1], kv0.y);
            FFMA2(s4[2], q2[(dg + 4) * 2], kv1.x);
            FFMA2(s4[3], q2[(dg + 4) * 2 + 1], kv1.y);
        }
        float2 f0 = *(float2*)&s4[0];
        float2 f1 = *(float2*)&s4[1];
        float2 f2 = *(float2*)&s4[2];
        float2 f3 = *(float2*)&s4[3];
        sc[n] = ((f0.x + f0.y) + (f1.x + f1.y) + (f2.x + f2.y) + (f3.x + f3.y))
                * scale;
    }

    float m = sc[0];
#pragma unroll
    for (int n = 1; n < 25; n++) m = fmaxf(m, sc[n]);
    float sum = 0.f;
#pragma unroll
    for (int n = 0; n < 25; n++) {
        float e = __expf(sc[n] - m);
        sc[n] = e;
        sum += e;
    }
    const float inv = 1.f / sum;

    u64 o2[16];
#pragma unroll
    for (int i = 0; i < 16; i++) o2[i] = 0ull;
#pragma unroll
    for (int n = 0; n < 25; n++) {
        const int di = n / 5, dj = n - 5 * (n / 5);
        const int pix = (ty + di) * PWT + (tx + dj);
        u64 w2;
        PACK2(w2, sc[n]);
#pragma unroll
        for (int dg = 0; dg < 8; dg++) {
            ulonglong2 vv = *(const ulonglong2*)&vs4[dg * DGS + pix];
            FFMA2(o2[dg * 2], w2, vv.x);
            FFMA2(o2[dg * 2 + 1], w2, vv.y);
        }
    }

    uint32_t hu[16], lu[16];
#pragma unroll
    for (int i = 0; i < 16; i++) {
        float2 f = *(float2*)&o2[i];
        float a = f.x * inv, bb = f.y * inv;
        __nv_bfloat16 ha = __float2bfloat16(a), hb = __float2bfloat16(bb);
        float la = a - __bfloat162float(ha);
        float lb = bb - __bfloat162float(hb);
        PACK_BF16X2(hu[i], a, bb);
        PACK_BF16X2(lu[i], la, lb);
    }
    __nv_bfloat16* oh = g_ohi + ((size_t)b * HW + p) * INNER + h * DHEAD;
    __nv_bfloat16* ol = g_olo + ((size_t)b * HW + p) * INNER + h * DHEAD;
#pragma unroll
    for (int cc = 0; cc < 4; cc++) {
        *(uint4*)(oh + cc * 8) = make_uint4(hu[4 * cc], hu[4 * cc + 1],
                                            hu[4 * cc + 2], hu[4 * cc + 3]);
        *(uint4*)(ol + cc * 8) = make_uint4(lu[4 * cc], lu[4 * cc + 1],
                                            lu[4 * cc + 2], lu[4 * cc + 3]);
    }
}

// ---------------------------------------------------------------------------
// Kernel 3: proj. A = wproj hi/lo, B = attn-out hi/lo. D[c][p] -> NCHW.
// ---------------------------------------------------------------------------
__global__ __launch_bounds__(256) void proj_mma_kernel(float* __restrict__ outp)
{
    extern __shared__ char sm[];
    const uint32_t smb = smem_u32(sm);
    const int tid = threadIdx.x, wid = tid >> 5, lane = tid & 31;
    const int pb = blockIdx.x, b = blockIdx.y;
    const int p0 = pb * 128;

    const __nv_bfloat16* ah = g_whi + 3 * 16384;
    const __nv_bfloat16* al = g_wlo + 3 * 16384;
    const __nv_bfloat16* bh = g_ohi + ((size_t)b * HW + p0) * INNER;
    const __nv_bfloat16* bl = g_olo + ((size_t)b * HW + p0) * INNER;

    stage_tile(smb + 0 * TILE, ah, tid);
    stage_tile(smb + 2 * TILE, bh, tid);
    CP_COMMIT();
    stage_tile(smb + 1 * TILE, al, tid);
    stage_tile(smb + 3 * TILE, bl, tid);
    CP_COMMIT();

    float acc[16][4];
#pragma unroll
    for (int i = 0; i < 16; i++)
#pragma unroll
        for (int j = 0; j < 4; j++) acc[i][j] = 0.f;

    const int mwarp = (wid >> 2) * 64, nwarp = (wid & 3) * 32;

    CP_WAIT(1);
    __syncthreads();
    mma_tiles(smb + 0 * TILE, smb + 2 * TILE, lane, mwarp, nwarp, acc);
    CP_WAIT(0);
    __syncthreads();
    mma_tiles(smb + 0 * TILE, smb + 3 * TILE, lane, mwarp, nwarp, acc);
    mma_tiles(smb + 1 * TILE, smb + 2 * TILE, lane, mwarp, nwarp, acc);

    const int gid = lane >> 2, tig = lane & 3;
#pragma unroll
    for (int mt = 0; mt < 4; mt++) {
#pragma unroll
        for (int half = 0; half < 2; half++) {
            int c = mwarp + mt * 16 + gid + half * 8;
            float* dst = outp + ((size_t)b * C + c) * HW + p0;
#pragma unroll
            for (int nt = 0; nt < 4; nt++) {
                int col = nwarp + nt * 8 + 2 * tig;
                *(float2*)(dst + col) = make_float2(acc[mt * 4 + nt][half * 2],
                                                    acc[mt * 4 + nt][half * 2 + 1]);
            }
        }
    }
}

extern "C" void kernel_launch(void* const* d_in, const int* in_sizes, int n_in,
                              void* d_out, int out_size)
{
    const float* x     = (const float*)d_in[0];
    const float* wq    = (const float*)d_in[1];
    const float* wk    = (const float*)d_in[2];
    const float* wv    = (const float*)d_in[3];
    const float* wproj = (const float*)d_in[4];
    float* outp = (float*)d_out;

    cudaFuncSetAttribute(attn_kernel,
                         cudaFuncAttributeMaxDynamicSharedMemorySize, ATTN_SMEM);
    cudaFuncSetAttribute(qkv_mma_kernel,
                         cudaFuncAttributeMaxDynamicSharedMemorySize, GEMM_SMEM);
    cudaFuncSetAttribute(proj_mma_kernel,
                         cudaFuncAttributeMaxDynamicSharedMemorySize, GEMM_SMEM);

    wbake_kernel<<<dim3(64, 4), 256>>>(wq, wk, wv, wproj);
    xsplit_kernel<<<dim3(HW / 32, C / 32, BATCH), 256>>>(x);
    qkv_mma_kernel<<<dim3(NTILES, 3, BATCH), 256, GEMM_SMEM>>>();
    attn_kernel<<<dim3(W / TX, H / TY, HEADS * BATCH), 256, ATTN_SMEM>>>();
    proj_mma_kernel<<<dim3(NTILES, BATCH), 256, GEMM_SMEM>>>(outp);
}

// round 7
// speedup vs baseline: 1.0010x; 1.0010x over previous
#include <cuda_runtime.h>
#include <cuda_bf16.h>
#include <cstdint>

#define BATCH 2
#define C 128
#define H 96
#define W 96
#define HEADS 4
#define DHEAD 32
#define PAD 2
#define INNER 128
#define HW (H * W)
#define HP (H + 2 * PAD)
#define WP (W + 2 * PAD)
#define NTILES (HW / 128)   // 72

typedef unsigned long long u64;

// fp32 scratch
__device__ float g_q[(size_t)BATCH * HW * INNER];          // [b][p][inner]
__device__ float g_kpad[(size_t)BATCH * HP * WP * INNER];  // [b][yp][xp][inner]
__device__ float g_vpad[(size_t)BATCH * HP * WP * INNER];

// bf16 hi/lo operand images
__device__ __nv_bfloat16 g_xhi[(size_t)BATCH * HW * C];    // [b][p][c]
__device__ __nv_bfloat16 g_xlo[(size_t)BATCH * HW * C];
__device__ __nv_bfloat16 g_whi[4 * C * INNER];             // [mat][o][c]
__device__ __nv_bfloat16 g_wlo[4 * C * INNER];
__device__ __nv_bfloat16 g_ohi[(size_t)BATCH * HW * INNER];// [b][p][inner]
__device__ __nv_bfloat16 g_olo[(size_t)BATCH * HW * INNER];

#define FFMA2(d, a, b) \
    asm("fma.rn.f32x2 %0, %1, %2, %0;" : "+l"(d) : "l"(a), "l"(b))
#define PACK2(d, s) \
    asm("mov.b64 %0, {%1, %1};" : "=l"(d) : "f"(s))

__device__ __forceinline__ void cp16(uint32_t smem, const void* g) {
    asm volatile("cp.async.cg.shared.global [%0], [%1], 16;" :: "r"(smem), "l"(g));
}
#define CP_COMMIT() asm volatile("cp.async.commit_group;")
#define CP_WAIT(n)  asm volatile("cp.async.wait_group %0;" :: "n"(n))

__device__ __forceinline__ uint32_t smem_u32(const void* p) {
    uint32_t a;
    asm("{ .reg .u64 t; cvta.to.shared.u64 t, %1; cvt.u32.u64 %0, t; }"
        : "=r"(a) : "l"(p));
    return a;
}

// pack two f32 -> bf16x2 reg, v0 in low half (memory element 0)
#define PACK_BF16X2(res, v0, v1) \
    asm("cvt.rn.bf16x2.f32 %0, %1, %2;" : "=r"(res) : "f"(v1), "f"(v0))

#define LDM_X4(r, addr) \
    asm volatile("ldmatrix.sync.aligned.m8n8.x4.shared.b16 {%0,%1,%2,%3}, [%4];" \
        : "=r"((r)[0]), "=r"((r)[1]), "=r"((r)[2]), "=r"((r)[3]) : "r"(addr))

#define MMA16816(d, a, bp) \
    asm volatile("mma.sync.aligned.m16n8k16.row.col.f32.bf16.bf16.f32 " \
        "{%0,%1,%2,%3}, {%4,%5,%6,%7}, {%8,%9}, {%0,%1,%2,%3};" \
        : "+f"((d)[0]), "+f"((d)[1]), "+f"((d)[2]), "+f"((d)[3]) \
        : "r"((a)[0]), "r"((a)[1]), "r"((a)[2]), "r"((a)[3]), \
          "r"((bp)[0]), "r"((bp)[1]))

// smem tile: 128 rows x 128 bf16, row stride 272B (17*16 -> conflict-free)
#define TROW 272
#define TILE (128 * TROW)
#define GEMM_SMEM (4 * TILE)   // 139264

// ---------------------------------------------------------------------------
// Kernel A: split x (f32 [b][c][p]) -> g_xhi/g_xlo (bf16 [b][p][c])
// ---------------------------------------------------------------------------
__global__ __launch_bounds__(256) void xsplit_kernel(const float* __restrict__ x)
{
    __shared__ float t[32][33];
    const int p0 = blockIdx.x * 32, c0 = blockIdx.y * 32, b = blockIdx.z;
    const int tl = threadIdx.x & 31, th = threadIdx.x >> 5;
#pragma unroll
    for (int i = 0; i < 4; i++) {
        int c = th + i * 8;
        t[c][tl] = x[((size_t)b * C + c0 + c) * HW + p0 + tl];
    }
    __syncthreads();
#pragma unroll
    for (int i = 0; i < 4; i++) {
        int p = th + i * 8;
        float v = t[tl][p];
        __nv_bfloat16 hb = __float2bfloat16(v);
        float lov = v - __bfloat162float(hb);
        size_t off = ((size_t)b * HW + p0 + p) * C + c0 + tl;
        g_xhi[off] = hb;
        g_xlo[off] = __float2bfloat16(lov);
    }
}

// ---------------------------------------------------------------------------
// Kernel B: bake weights -> bf16 hi/lo [mat][o][c]
// ---------------------------------------------------------------------------
__global__ __launch_bounds__(256) void wbake_kernel(
    const float* __restrict__ wq, const float* __restrict__ wk,
    const float* __restrict__ wv, const float* __restrict__ wp)
{
    const int mat = blockIdx.y;
    const float* __restrict__ src =
        (mat == 0) ? wq : (mat == 1) ? wk : (mat == 2) ? wv : wp;
    int idx = blockIdx.x * 256 + threadIdx.x;
    float w = src[idx];
    __nv_bfloat16 hb = __float2bfloat16(w);
    float lov = w - __bfloat162float(hb);
    g_whi[mat * 16384 + idx] = hb;
    g_wlo[mat * 16384 + idx] = __float2bfloat16(lov);
}

// ---------------------------------------------------------------------------
// Shared HMMA mainloop (validated in R5)
// ---------------------------------------------------------------------------
__device__ __forceinline__ void mma_tiles(
    uint32_t Abase, uint32_t Bbase, int lane, int mwarp, int nwarp,
    float (*acc)[4])
{
    const uint32_t arow0 = Abase + (uint32_t)(mwarp + (lane & 15)) * TROW
                         + ((lane >> 4) & 1) * 16;
    const uint32_t brow0 = Bbase
                         + (uint32_t)(nwarp + ((lane >> 4) << 3) + (lane & 7)) * TROW
                         + ((lane >> 3) & 1) * 16;
#pragma unroll
    for (int k0 = 0; k0 < 8; k0++) {
        uint32_t a[4][4], bq[2][4];
#pragma unroll
        for (int mt = 0; mt < 4; mt++)
            LDM_X4(a[mt], arow0 + k0 * 32 + mt * (16 * TROW));
#pragma unroll
        for (int n2 = 0; n2 < 2; n2++)
            LDM_X4(bq[n2], brow0 + k0 * 32 + n2 * (16 * TROW));
#pragma unroll
        for (int mt = 0; mt < 4; mt++)
#pragma unroll
            for (int nt = 0; nt < 4; nt++)
                MMA16816(acc[mt * 4 + nt], a[mt], &bq[nt >> 1][(nt & 1) * 2]);
    }
}

__device__ __forceinline__ void stage_tile(
    uint32_t dst, const __nv_bfloat16* __restrict__ src, int tid)
{
    for (int i = tid; i < 2048; i += 256) {
        int r = i >> 4, ch = i & 15;
        cp16(dst + r * TROW + ch * 16, src + r * 128 + ch * 8);
    }
}

// ---------------------------------------------------------------------------
// Kernel 1: QKV. A = X (pixels) hi/lo, B = W hi/lo. D[p][o].
// ---------------------------------------------------------------------------
__global__ __launch_bounds__(256) void qkv_mma_kernel()
{
    extern __shared__ char sm[];
    const uint32_t smb = smem_u32(sm);
    const int tid = threadIdx.x, wid = tid >> 5, lane = tid & 31;
    const int pb = blockIdx.x, mat = blockIdx.y, b = blockIdx.z;
    const int p0 = pb * 128;

    const __nv_bfloat16* xh = g_xhi + ((size_t)b * HW + p0) * C;
    const __nv_bfloat16* xl = g_xlo + ((size_t)b * HW + p0) * C;
    const __nv_bfloat16* wh = g_whi + mat * 16384;
    const __nv_bfloat16* wl = g_wlo + mat * 16384;

    stage_tile(smb + 0 * TILE, xh, tid);
    stage_tile(smb + 2 * TILE, wh, tid);
    CP_COMMIT();
    stage_tile(smb + 1 * TILE, xl, tid);
    stage_tile(smb + 3 * TILE, wl, tid);
    CP_COMMIT();

    float acc[16][4];
#pragma unroll
    for (int i = 0; i < 16; i++)
#pragma unroll
        for (int j = 0; j < 4; j++) acc[i][j] = 0.f;

    const int mwarp = (wid >> 2) * 64, nwarp = (wid & 3) * 32;

    CP_WAIT(1);
    __syncthreads();
    mma_tiles(smb + 0 * TILE, smb + 2 * TILE, lane, mwarp, nwarp, acc);
    CP_WAIT(0);
    __syncthreads();
    mma_tiles(smb + 0 * TILE, smb + 3 * TILE, lane, mwarp, nwarp, acc);
    mma_tiles(smb + 1 * TILE, smb + 2 * TILE, lane, mwarp, nwarp, acc);

    const int gid = lane >> 2, tig = lane & 3;
#pragma unroll
    for (int mt = 0; mt < 4; mt++) {
#pragma unroll
        for (int half = 0; half < 2; half++) {
            int r = mwarp + mt * 16 + gid + half * 8;
            int p = p0 + r;
            float* dst;
            if (mat == 0) {
                dst = g_q + ((size_t)b * HW + p) * INNER;
            } else {
                int yy = p / W, xx = p - yy * W;
                float* base = (mat == 1) ? g_kpad : g_vpad;
                dst = base + (((size_t)b * HP + yy + PAD) * WP + (xx + PAD)) * INNER;
            }
#pragma unroll
            for (int nt = 0; nt < 4; nt++) {
                int o = nwarp + nt * 8 + 2 * tig;
                *(float2*)(dst + o) = make_float2(acc[mt * 4 + nt][half * 2],
                                                  acc[mt * 4 + nt][half * 2 + 1]);
            }
        }
    }
}

// ---------------------------------------------------------------------------
// Kernel 2: window attention, d-split: 2 threads per (pixel, head), each
// owning 16 of 32 d-channels. Tile 32x4, halo 36x8 in smem (74KB),
// 3 blocks/SM. Scores joined with one shfl.xor(1) per tap.
// ---------------------------------------------------------------------------
#define TX 32
#define TY 4
#define PWT (TX + 4)     // 36
#define PHT (TY + 4)     // 8
#define NPIX (PWT * PHT) // 288
#define DGS 289
#define ATTN_SMEM (2 * 8 * DGS * 16)   // 73984

__global__ __launch_bounds__(256, 3) void attn_kernel()
{
    extern __shared__ float4 sm4[];
    float4* ks4 = sm4;
    float4* vs4 = sm4 + 8 * DGS;
    const uint32_t smbk = smem_u32(ks4);
    const uint32_t smbv = smem_u32(vs4);

    const int t  = threadIdx.x;
    const int x0 = blockIdx.x * TX;
    const int y0 = blockIdx.y * TY;
    const int h  = blockIdx.z & 3;
    const int b  = blockIdx.z >> 2;

    const float* __restrict__ kg =
        g_kpad + (((size_t)b * HP + y0) * WP + x0) * INNER + h * DHEAD;
    const float* __restrict__ vg =
        g_vpad + (((size_t)b * HP + y0) * WP + x0) * INNER + h * DHEAD;

    // fill halo: 288 pix x 8 dg, both arrays; 2304 cp16 each, 9 per thread
#pragma unroll
    for (int i = t; i < NPIX * 8; i += 256) {
        int pp = i >> 3, dg = i & 7;
        int py = pp / PWT, px = pp - py * PWT;
        size_t goff = ((size_t)py * WP + px) * INNER + dg * 4;
        cp16(smbk + (uint32_t)(dg * DGS + pp) * 16, kg + goff);
        cp16(smbv + (uint32_t)(dg * DGS + pp) * 16, vg + goff);
    }
    CP_COMMIT();

    const int hh  = t & 1;        // d-half: 0 -> d[0:16), 1 -> d[16:32)
    const int pix = t >> 1;       // 0..127
    const int tx  = pix & 31, ty = pix >> 5;
    const int p   = (y0 + ty) * W + x0 + tx;
    const int dgb = hh * 4;       // dg planes owned by this half

    // q half: 16 floats
    u64 q2[8];
    const float* qp = g_q + ((size_t)b * HW + p) * INNER + h * DHEAD + hh * 16;
#pragma unroll
    for (int i = 0; i < 4; i++) {
        ulonglong2 v = *(const ulonglong2*)(qp + i * 4);
        q2[2 * i] = v.x; q2[2 * i + 1] = v.y;
    }

    CP_WAIT(0);
    __syncthreads();

    const float scale = 0.17677669529663687f;  // 1/sqrt(32)
    float sc[25];
#pragma unroll
    for (int n = 0; n < 25; n++) {
        const int di = n / 5, dj = n - 5 * (n / 5);
        const int pixi = (ty + di) * PWT + (tx + dj);
        u64 s0 = 0ull, s1 = 0ull;
#pragma unroll
        for (int dg = 0; dg < 4; dg++) {
            ulonglong2 kv = *(const ulonglong2*)&ks4[(dgb + dg) * DGS + pixi];
            FFMA2(s0, q2[2 * dg], kv.x);
            FFMA2(s1, q2[2 * dg + 1], kv.y);
        }
        float2 f0 = *(float2*)&s0;
        float2 f1 = *(float2*)&s1;
        float part = (f0.x + f0.y) + (f1.x + f1.y);
        part += __shfl_xor_sync(0xffffffffu, part, 1);
        sc[n] = part * scale;
    }

    float m = sc[0];
#pragma unroll
    for (int n = 1; n < 25; n++) m = fmaxf(m, sc[n]);
    float sum = 0.f;
#pragma unroll
    for (int n = 0; n < 25; n++) {
        float e = __expf(sc[n] - m);
        sc[n] = e;
        sum += e;
    }
    const float inv = 1.f / sum;

    u64 o2[8];
#pragma unroll
    for (int i = 0; i < 8; i++) o2[i] = 0ull;
#pragma unroll
    for (int n = 0; n < 25; n++) {
        const int di = n / 5, dj = n - 5 * (n / 5);
        const int pixi = (ty + di) * PWT + (tx + dj);
        u64 w2;
        PACK2(w2, sc[n]);
#pragma unroll
        for (int dg = 0; dg < 4; dg++) {
            ulonglong2 vv = *(const ulonglong2*)&vs4[(dgb + dg) * DGS + pixi];
            FFMA2(o2[2 * dg], w2, vv.x);
            FFMA2(o2[2 * dg + 1], w2, vv.y);
        }
    }

    // split to bf16 hi/lo, write this half's 16 channels
    uint32_t hu[8], lu[8];
#pragma unroll
    for (int i = 0; i < 8; i++) {
        float2 f = *(float2*)&o2[i];
        float a = f.x * inv, bb = f.y * inv;
        __nv_bfloat16 ha = __float2bfloat16(a), hb = __float2bfloat16(bb);
        float la = a - __bfloat162float(ha);
        float lb = bb - __bfloat162float(hb);
        PACK_BF16X2(hu[i], a, bb);
        PACK_BF16X2(lu[i], la, lb);
    }
    __nv_bfloat16* oh = g_ohi + ((size_t)b * HW + p) * INNER + h * DHEAD + hh * 16;
    __nv_bfloat16* ol = g_olo + ((size_t)b * HW + p) * INNER + h * DHEAD + hh * 16;
#pragma unroll
    for (int cc = 0; cc < 2; cc++) {
        *(uint4*)(oh + cc * 8) = make_uint4(hu[4 * cc], hu[4 * cc + 1],
                                            hu[4 * cc + 2], hu[4 * cc + 3]);
        *(uint4*)(ol + cc * 8) = make_uint4(lu[4 * cc], lu[4 * cc + 1],
                                            lu[4 * cc + 2], lu[4 * cc + 3]);
    }
}

// ---------------------------------------------------------------------------
// Kernel 3: proj. A = wproj hi/lo, B = attn-out hi/lo. D[c][p] -> NCHW.
// ---------------------------------------------------------------------------
__global__ __launch_bounds__(256) void proj_mma_kernel(float* __restrict__ outp)
{
    extern __shared__ char sm[];
    const uint32_t smb = smem_u32(sm);
    const int tid = threadIdx.x, wid = tid >> 5, lane = tid & 31;
    const int pb = blockIdx.x, b = blockIdx.y;
    const int p0 = pb * 128;

    const __nv_bfloat16* ah = g_whi + 3 * 16384;
    const __nv_bfloat16* al = g_wlo + 3 * 16384;
    const __nv_bfloat16* bh = g_ohi + ((size_t)b * HW + p0) * INNER;
    const __nv_bfloat16* bl = g_olo + ((size_t)b * HW + p0) * INNER;

    stage_tile(smb + 0 * TILE, ah, tid);
    stage_tile(smb + 2 * TILE, bh, tid);
    CP_COMMIT();
    stage_tile(smb + 1 * TILE, al, tid);
    stage_tile(smb + 3 * TILE, bl, tid);
    CP_COMMIT();

    float acc[16][4];
#pragma unroll
    for (int i = 0; i < 16; i++)
#pragma unroll
        for (int j = 0; j < 4; j++) acc[i][j] = 0.f;

    const int mwarp = (wid >> 2) * 64, nwarp = (wid & 3) * 32;

    CP_WAIT(1);
    __syncthreads();
    mma_tiles(smb + 0 * TILE, smb + 2 * TILE, lane, mwarp, nwarp, acc);
    CP_WAIT(0);
    __syncthreads();
    mma_tiles(smb + 0 * TILE, smb + 3 * TILE, lane, mwarp, nwarp, acc);
    mma_tiles(smb + 1 * TILE, smb + 2 * TILE, lane, mwarp, nwarp, acc);

    const int gid = lane >> 2, tig = lane & 3;
#pragma unroll
    for (int mt = 0; mt < 4; mt++) {
#pragma unroll
        for (int half = 0; half < 2; half++) {
            int c = mwarp + mt * 16 + gid + half * 8;
            float* dst = outp + ((size_t)b * C + c) * HW + p0;
#pragma unroll
            for (int nt = 0; nt < 4; nt++) {
                int col = nwarp + nt * 8 + 2 * tig;
                *(float2*)(dst + col) = make_float2(acc[mt * 4 + nt][half * 2],
                                                    acc[mt * 4 + nt][half * 2 + 1]);
            }
        }
    }
}

extern "C" void kernel_launch(void* const* d_in, const int* in_sizes, int n_in,
                              void* d_out, int out_size)
{
    const float* x     = (const float*)d_in[0];
    const float* wq    = (const float*)d_in[1];
    const float* wk    = (const float*)d_in[2];
    const float* wv    = (const float*)d_in[3];
    const float* wproj = (const float*)d_in[4];
    float* outp = (float*)d_out;

    cudaFuncSetAttribute(attn_kernel,
                         cudaFuncAttributeMaxDynamicSharedMemorySize, ATTN_SMEM);
    cudaFuncSetAttribute(qkv_mma_kernel,
                         cudaFuncAttributeMaxDynamicSharedMemorySize, GEMM_SMEM);
    cudaFuncSetAttribute(proj_mma_kernel,
                         cudaFuncAttributeMaxDynamicSharedMemorySize, GEMM_SMEM);

    wbake_kernel<<<dim3(64, 4), 256>>>(wq, wk, wv, wproj);
    xsplit_kernel<<<dim3(HW / 32, C / 32, BATCH), 256>>>(x);
    qkv_mma_kernel<<<dim3(NTILES, 3, BATCH), 256, GEMM_SMEM>>>();
    attn_kernel<<<dim3(W / TX, H / TY, HEADS * BATCH), 256, ATTN_SMEM>>>();
    proj_mma_kernel<<<dim3(NTILES, BATCH), 256, GEMM_SMEM>>>(outp);
}

// round 8
// speedup vs baseline: 1.1079x; 1.1068x over previous
#include <cuda_runtime.h>
#include <cuda_bf16.h>
#include <cstdint>

#define BATCH 2
#define C 128
#define H 96
#define W 96
#define HEADS 4
#define DHEAD 32
#define PAD 2
#define INNER 128
#define HW (H * W)
#define HP (H + 2 * PAD)
#define WP (W + 2 * PAD)
#define NTILES (HW / 128)   // 72

typedef unsigned long long u64;

// fp32 scratch
__device__ float g_q[(size_t)BATCH * HW * INNER];          // [b][p][inner]
__device__ float g_kpad[(size_t)BATCH * HP * WP * INNER];  // [b][yp][xp][inner]
__device__ float g_vpad[(size_t)BATCH * HP * WP * INNER];

// bf16 hi/lo operand images
__device__ __nv_bfloat16 g_xhi[(size_t)BATCH * HW * C];    // [b][p][c]
__device__ __nv_bfloat16 g_xlo[(size_t)BATCH * HW * C];
__device__ __nv_bfloat16 g_whi[4 * C * INNER];             // [mat][o][c]
__device__ __nv_bfloat16 g_wlo[4 * C * INNER];
__device__ __nv_bfloat16 g_ohi[(size_t)BATCH * HW * INNER];// [b][p][inner]
__device__ __nv_bfloat16 g_olo[(size_t)BATCH * HW * INNER];

#define FFMA2(d, a, b) \
    asm("fma.rn.f32x2 %0, %1, %2, %0;" : "+l"(d) : "l"(a), "l"(b))
#define PACK2(d, s) \
    asm("mov.b64 %0, {%1, %1};" : "=l"(d) : "f"(s))

__device__ __forceinline__ void cp16(uint32_t smem, const void* g) {
    asm volatile("cp.async.cg.shared.global [%0], [%1], 16;" :: "r"(smem), "l"(g));
}
#define CP_COMMIT() asm volatile("cp.async.commit_group;")
#define CP_WAIT(n)  asm volatile("cp.async.wait_group %0;" :: "n"(n))

__device__ __forceinline__ uint32_t smem_u32(const void* p) {
    uint32_t a;
    asm("{ .reg .u64 t; cvta.to.shared.u64 t, %1; cvt.u32.u64 %0, t; }"
        : "=r"(a) : "l"(p));
    return a;
}

// pack two f32 -> bf16x2 reg, v0 in low half (memory element 0)
#define PACK_BF16X2(res, v0, v1) \
    asm("cvt.rn.bf16x2.f32 %0, %1, %2;" : "=r"(res) : "f"(v1), "f"(v0))

#define LDM_X4(r, addr) \
    asm volatile("ldmatrix.sync.aligned.m8n8.x4.shared.b16 {%0,%1,%2,%3}, [%4];" \
        : "=r"((r)[0]), "=r"((r)[1]), "=r"((r)[2]), "=r"((r)[3]) : "r"(addr))

#define MMA16816(d, a, bp) \
    asm volatile("mma.sync.aligned.m16n8k16.row.col.f32.bf16.bf16.f32 " \
        "{%0,%1,%2,%3}, {%4,%5,%6,%7}, {%8,%9}, {%0,%1,%2,%3};" \
        : "+f"((d)[0]), "+f"((d)[1]), "+f"((d)[2]), "+f"((d)[3]) \
        : "r"((a)[0]), "r"((a)[1]), "r"((a)[2]), "r"((a)[3]), \
          "r"((bp)[0]), "r"((bp)[1]))

// smem tile: 128 rows x 128 bf16, row stride 272B (17*16 -> conflict-free)
#define TROW 272
#define TILE (128 * TROW)
#define GEMM_SMEM (4 * TILE)   // 139264

// ---------------------------------------------------------------------------
// Kernel A: split x (f32 [b][c][p]) -> g_xhi/g_xlo (bf16 [b][p][c])
// ---------------------------------------------------------------------------
__global__ __launch_bounds__(256) void xsplit_kernel(const float* __restrict__ x)
{
    __shared__ float t[32][33];
    const int p0 = blockIdx.x * 32, c0 = blockIdx.y * 32, b = blockIdx.z;
    const int tl = threadIdx.x & 31, th = threadIdx.x >> 5;
#pragma unroll
    for (int i = 0; i < 4; i++) {
        int c = th + i * 8;
        t[c][tl] = x[((size_t)b * C + c0 + c) * HW + p0 + tl];
    }
    __syncthreads();
#pragma unroll
    for (int i = 0; i < 4; i++) {
        int p = th + i * 8;
        float v = t[tl][p];
        __nv_bfloat16 hb = __float2bfloat16(v);
        float lov = v - __bfloat162float(hb);
        size_t off = ((size_t)b * HW + p0 + p) * C + c0 + tl;
        g_xhi[off] = hb;
        g_xlo[off] = __float2bfloat16(lov);
    }
}

// ---------------------------------------------------------------------------
// Kernel B: bake weights -> bf16 hi/lo [mat][o][c]
// ---------------------------------------------------------------------------
__global__ __launch_bounds__(256) void wbake_kernel(
    const float* __restrict__ wq, const float* __restrict__ wk,
    const float* __restrict__ wv, const float* __restrict__ wp)
{
    const int mat = blockIdx.y;
    const float* __restrict__ src =
        (mat == 0) ? wq : (mat == 1) ? wk : (mat == 2) ? wv : wp;
    int idx = blockIdx.x * 256 + threadIdx.x;
    float w = src[idx];
    __nv_bfloat16 hb = __float2bfloat16(w);
    float lov = w - __bfloat162float(hb);
    g_whi[mat * 16384 + idx] = hb;
    g_wlo[mat * 16384 + idx] = __float2bfloat16(lov);
}

// ---------------------------------------------------------------------------
// Shared HMMA mainloop (validated in R5)
// ---------------------------------------------------------------------------
__device__ __forceinline__ void mma_tiles(
    uint32_t Abase, uint32_t Bbase, int lane, int mwarp, int nwarp,
    float (*acc)[4])
{
    const uint32_t arow0 = Abase + (uint32_t)(mwarp + (lane & 15)) * TROW
                         + ((lane >> 4) & 1) * 16;
    const uint32_t brow0 = Bbase
                         + (uint32_t)(nwarp + ((lane >> 4) << 3) + (lane & 7)) * TROW
                         + ((lane >> 3) & 1) * 16;
#pragma unroll
    for (int k0 = 0; k0 < 8; k0++) {
        uint32_t a[4][4], bq[2][4];
#pragma unroll
        for (int mt = 0; mt < 4; mt++)
            LDM_X4(a[mt], arow0 + k0 * 32 + mt * (16 * TROW));
#pragma unroll
        for (int n2 = 0; n2 < 2; n2++)
            LDM_X4(bq[n2], brow0 + k0 * 32 + n2 * (16 * TROW));
#pragma unroll
        for (int mt = 0; mt < 4; mt++)
#pragma unroll
            for (int nt = 0; nt < 4; nt++)
                MMA16816(acc[mt * 4 + nt], a[mt], &bq[nt >> 1][(nt & 1) * 2]);
    }
}

__device__ __forceinline__ void stage_tile(
    uint32_t dst, const __nv_bfloat16* __restrict__ src, int tid)
{
    for (int i = tid; i < 2048; i += 256) {
        int r = i >> 4, ch = i & 15;
        cp16(dst + r * TROW + ch * 16, src + r * 128 + ch * 8);
    }
}

// ---------------------------------------------------------------------------
// Kernel 1: QKV. A = X (pixels) hi/lo, B = W hi/lo. D[p][o].
// ---------------------------------------------------------------------------
__global__ __launch_bounds__(256) void qkv_mma_kernel()
{
    extern __shared__ char sm[];
    const uint32_t smb = smem_u32(sm);
    const int tid = threadIdx.x, wid = tid >> 5, lane = tid & 31;
    const int pb = blockIdx.x, mat = blockIdx.y, b = blockIdx.z;
    const int p0 = pb * 128;

    const __nv_bfloat16* xh = g_xhi + ((size_t)b * HW + p0) * C;
    const __nv_bfloat16* xl = g_xlo + ((size_t)b * HW + p0) * C;
    const __nv_bfloat16* wh = g_whi + mat * 16384;
    const __nv_bfloat16* wl = g_wlo + mat * 16384;

    stage_tile(smb + 0 * TILE, xh, tid);
    stage_tile(smb + 2 * TILE, wh, tid);
    CP_COMMIT();
    stage_tile(smb + 1 * TILE, xl, tid);
    stage_tile(smb + 3 * TILE, wl, tid);
    CP_COMMIT();

    float acc[16][4];
#pragma unroll
    for (int i = 0; i < 16; i++)
#pragma unroll
        for (int j = 0; j < 4; j++) acc[i][j] = 0.f;

    const int mwarp = (wid >> 2) * 64, nwarp = (wid & 3) * 32;

    CP_WAIT(1);
    __syncthreads();
    mma_tiles(smb + 0 * TILE, smb + 2 * TILE, lane, mwarp, nwarp, acc);
    CP_WAIT(0);
    __syncthreads();
    mma_tiles(smb + 0 * TILE, smb + 3 * TILE, lane, mwarp, nwarp, acc);
    mma_tiles(smb + 1 * TILE, smb + 2 * TILE, lane, mwarp, nwarp, acc);

    const int gid = lane >> 2, tig = lane & 3;
#pragma unroll
    for (int mt = 0; mt < 4; mt++) {
#pragma unroll
        for (int half = 0; half < 2; half++) {
            int r = mwarp + mt * 16 + gid + half * 8;
            int p = p0 + r;
            float* dst;
            if (mat == 0) {
                dst = g_q + ((size_t)b * HW + p) * INNER;
            } else {
                int yy = p / W, xx = p - yy * W;
                float* base = (mat == 1) ? g_kpad : g_vpad;
                dst = base + (((size_t)b * HP + yy + PAD) * WP + (xx + PAD)) * INNER;
            }
#pragma unroll
            for (int nt = 0; nt < 4; nt++) {
                int o = nwarp + nt * 8 + 2 * tig;
                *(float2*)(dst + o) = make_float2(acc[mt * 4 + nt][half * 2],
                                                  acc[mt * 4 + nt][half * 2 + 1]);
            }
        }
    }
}

// ---------------------------------------------------------------------------
// Kernel 2: window attention, pixel-pair + d-split.
// Block = 32x8 pixel tile, one (b,h). 256 threads:
//   thread = (pixel pair along x, d-half). Each thread computes 2 pixels
//   x 16 channels; the 5x6 tap union serves both pixels (30 tap loads
//   instead of 50). Scores joined across d-halves with shfl.xor(1).
// Halo 36x12 in smem, plane layout pl = dgl*2 + hh (conflict-free phases).
// ---------------------------------------------------------------------------
#define TX 32
#define TY 8
#define PWT (TX + 4)     // 36
#define PHT (TY + 4)     // 12
#define NPIX (PWT * PHT) // 432
#define DGS 433
#define ATTN_SMEM (2 * 8 * DGS * 16)   // 110848

__global__ __launch_bounds__(256, 2) void attn_kernel()
{
    extern __shared__ float4 sm4[];
    float4* ks4 = sm4;
    float4* vs4 = sm4 + 8 * DGS;
    const uint32_t smbk = smem_u32(ks4);
    const uint32_t smbv = smem_u32(vs4);

    const int t  = threadIdx.x;
    const int x0 = blockIdx.x * TX;
    const int y0 = blockIdx.y * TY;
    const int h  = blockIdx.z & 3;
    const int b  = blockIdx.z >> 2;

    const float* __restrict__ kg =
        g_kpad + (((size_t)b * HP + y0) * WP + x0) * INNER + h * DHEAD;
    const float* __restrict__ vg =
        g_vpad + (((size_t)b * HP + y0) * WP + x0) * INNER + h * DHEAD;

    // fill halo: pixel pp, channel group g (g = hh*4 + dgl) -> plane dgl*2+hh
#pragma unroll
    for (int i = t; i < NPIX * 8; i += 256) {
        int pp = i >> 3, g = i & 7;
        int py = pp / PWT, px = pp - py * PWT;
        int pl = ((g & 3) << 1) | (g >> 2);
        size_t goff = ((size_t)py * WP + px) * INNER + g * 4;
        cp16(smbk + (uint32_t)(pl * DGS + pp) * 16, kg + goff);
        cp16(smbv + (uint32_t)(pl * DGS + pp) * 16, vg + goff);
    }
    CP_COMMIT();

    const int hh   = t & 1;          // d-half
    const int pair = t >> 1;         // 0..127
    const int tx2  = pair & 15;      // pair column (pixels 2*tx2, 2*tx2+1)
    const int ty   = pair >> 4;      // 0..7
    const int p0p  = (y0 + ty) * W + x0 + 2 * tx2;

    // q for both pixels, this d-half (16 channels each)
    u64 q0[8], q1[8];
    {
        const float* qp0 = g_q + ((size_t)b * HW + p0p) * INNER + h * DHEAD + hh * 16;
        const float* qp1 = qp0 + INNER;
#pragma unroll
        for (int i = 0; i < 4; i++) {
            ulonglong2 v0 = *(const ulonglong2*)(qp0 + i * 4);
            ulonglong2 v1 = *(const ulonglong2*)(qp1 + i * 4);
            q0[2 * i] = v0.x; q0[2 * i + 1] = v0.y;
            q1[2 * i] = v1.x; q1[2 * i + 1] = v1.y;
        }
    }

    CP_WAIT(0);
    __syncthreads();

    // score partials (this half): 25 per pixel
    float s0[25], s1[25];
#pragma unroll
    for (int di = 0; di < 5; di++) {
#pragma unroll
        for (int djj = 0; djj < 6; djj++) {
            const int pixi = (ty + di) * PWT + 2 * tx2 + djj;
            u64 kk[8];
#pragma unroll
            for (int dgl = 0; dgl < 4; dgl++) {
                ulonglong2 kv = *(const ulonglong2*)&ks4[(dgl * 2 + hh) * DGS + pixi];
                kk[2 * dgl] = kv.x; kk[2 * dgl + 1] = kv.y;
            }
            if (djj < 5) {
                u64 a0 = 0ull, a1 = 0ull;
#pragma unroll
                for (int j = 0; j < 4; j++) {
                    FFMA2(a0, q0[2 * j], kk[2 * j]);
                    FFMA2(a1, q0[2 * j + 1], kk[2 * j + 1]);
                }
                float2 fa = *(float2*)&a0, fb = *(float2*)&a1;
                s0[di * 5 + djj] = (fa.x + fa.y) + (fb.x + fb.y);
            }
            if (djj > 0) {
                u64 a0 = 0ull, a1 = 0ull;
#pragma unroll
                for (int j = 0; j < 4; j++) {
                    FFMA2(a0, q1[2 * j], kk[2 * j]);
                    FFMA2(a1, q1[2 * j + 1], kk[2 * j + 1]);
                }
                float2 fa = *(float2*)&a0, fb = *(float2*)&a1;
                s1[di * 5 + djj - 1] = (fa.x + fa.y) + (fb.x + fb.y);
            }
        }
    }

    // join d-halves
    const float scale = 0.17677669529663687f;  // 1/sqrt(32)
#pragma unroll
    for (int n = 0; n < 25; n++) {
        s0[n] = (s0[n] + __shfl_xor_sync(0xffffffffu, s0[n], 1)) * scale;
        s1[n] = (s1[n] + __shfl_xor_sync(0xffffffffu, s1[n], 1)) * scale;
    }

    // softmax (both pixels; duplicated across halves)
    float m0 = s0[0], m1 = s1[0];
#pragma unroll
    for (int n = 1; n < 25; n++) {
        m0 = fmaxf(m0, s0[n]);
        m1 = fmaxf(m1, s1[n]);
    }
    float sum0 = 0.f, sum1 = 0.f;
#pragma unroll
    for (int n = 0; n < 25; n++) {
        float e0 = __expf(s0[n] - m0);
        float e1 = __expf(s1[n] - m1);
        s0[n] = e0; s1[n] = e1;
        sum0 += e0; sum1 += e1;
    }
    const float inv0 = 1.f / sum0, inv1 = 1.f / sum1;

    // AV: this half's 16 channels for both pixels
    u64 o0[8], o1[8];
#pragma unroll
    for (int i = 0; i < 8; i++) { o0[i] = 0ull; o1[i] = 0ull; }
#pragma unroll
    for (int di = 0; di < 5; di++) {
#pragma unroll
        for (int djj = 0; djj < 6; djj++) {
            const int pixi = (ty + di) * PWT + 2 * tx2 + djj;
            u64 vv[8];
#pragma unroll
            for (int dgl = 0; dgl < 4; dgl++) {
                ulonglong2 vq = *(const ulonglong2*)&vs4[(dgl * 2 + hh) * DGS + pixi];
                vv[2 * dgl] = vq.x; vv[2 * dgl + 1] = vq.y;
            }
            if (djj < 5) {
                u64 w2;
                PACK2(w2, s0[di * 5 + djj]);
#pragma unroll
                for (int j = 0; j < 8; j++) FFMA2(o0[j], w2, vv[j]);
            }
            if (djj > 0) {
                u64 w2;
                PACK2(w2, s1[di * 5 + djj - 1]);
#pragma unroll
                for (int j = 0; j < 8; j++) FFMA2(o1[j], w2, vv[j]);
            }
        }
    }

    // split to bf16 hi/lo and store both pixels' 16-channel halves
#pragma unroll
    for (int px = 0; px < 2; px++) {
        const u64* oo = px ? o1 : o0;
        const float inv = px ? inv1 : inv0;
        uint32_t hu[8], lu[8];
#pragma unroll
        for (int i = 0; i < 8; i++) {
            float2 f = *(float2*)&oo[i];
            float a = f.x * inv, bb = f.y * inv;
            __nv_bfloat16 ha = __float2bfloat16(a), hb = __float2bfloat16(bb);
            float la = a - __bfloat162float(ha);
            float lb = bb - __bfloat162float(hb);
            PACK_BF16X2(hu[i], a, bb);
            PACK_BF16X2(lu[i], la, lb);
        }
        __nv_bfloat16* oh = g_ohi + ((size_t)b * HW + p0p + px) * INNER + h * DHEAD + hh * 16;
        __nv_bfloat16* ol = g_olo + ((size_t)b * HW + p0p + px) * INNER + h * DHEAD + hh * 16;
#pragma unroll
        for (int cc = 0; cc < 2; cc++) {
            *(uint4*)(oh + cc * 8) = make_uint4(hu[4 * cc], hu[4 * cc + 1],
                                                hu[4 * cc + 2], hu[4 * cc + 3]);
            *(uint4*)(ol + cc * 8) = make_uint4(lu[4 * cc], lu[4 * cc + 1],
                                                lu[4 * cc + 2], lu[4 * cc + 3]);
        }
    }
}

// ---------------------------------------------------------------------------
// Kernel 3: proj. A = wproj hi/lo, B = attn-out hi/lo. D[c][p] -> NCHW.
// ---------------------------------------------------------------------------
__global__ __launch_bounds__(256) void proj_mma_kernel(float* __restrict__ outp)
{
    extern __shared__ char sm[];
    const uint32_t smb = smem_u32(sm);
    const int tid = threadIdx.x, wid = tid >> 5, lane = tid & 31;
    const int pb = blockIdx.x, b = blockIdx.y;
    const int p0 = pb * 128;

    const __nv_bfloat16* ah = g_whi + 3 * 16384;
    const __nv_bfloat16* al = g_wlo + 3 * 16384;
    const __nv_bfloat16* bh = g_ohi + ((size_t)b * HW + p0) * INNER;
    const __nv_bfloat16* bl = g_olo + ((size_t)b * HW + p0) * INNER;

    stage_tile(smb + 0 * TILE, ah, tid);
    stage_tile(smb + 2 * TILE, bh, tid);
    CP_COMMIT();
    stage_tile(smb + 1 * TILE, al, tid);
    stage_tile(smb + 3 * TILE, bl, tid);
    CP_COMMIT();

    float acc[16][4];
#pragma unroll
    for (int i = 0; i < 16; i++)
#pragma unroll
        for (int j = 0; j < 4; j++) acc[i][j] = 0.f;

    const int mwarp = (wid >> 2) * 64, nwarp = (wid & 3) * 32;

    CP_WAIT(1);
    __syncthreads();
    mma_tiles(smb + 0 * TILE, smb + 2 * TILE, lane, mwarp, nwarp, acc);
    CP_WAIT(0);
    __syncthreads();
    mma_tiles(smb + 0 * TILE, smb + 3 * TILE, lane, mwarp, nwarp, acc);
    mma_tiles(smb + 1 * TILE, smb + 2 * TILE, lane, mwarp, nwarp, acc);

    const int gid = lane >> 2, tig = lane & 3;
#pragma unroll
    for (int mt = 0; mt < 4; mt++) {
#pragma unroll
        for (int half = 0; half < 2; half++) {
            int c = mwarp + mt * 16 + gid + half * 8;
            float* dst = outp + ((size_t)b * C + c) * HW + p0;
#pragma unroll
            for (int nt = 0; nt < 4; nt++) {
                int col = nwarp + nt * 8 + 2 * tig;
                *(float2*)(dst + col) = make_float2(acc[mt * 4 + nt][half * 2],
                                                    acc[mt * 4 + nt][half * 2 + 1]);
            }
        }
    }
}

extern "C" void kernel_launch(void* const* d_in, const int* in_sizes, int n_in,
                              void* d_out, int out_size)
{
    const float* x     = (const float*)d_in[0];
    const float* wq    = (const float*)d_in[1];
    const float* wk    = (const float*)d_in[2];
    const float* wv    = (const float*)d_in[3];
    const float* wproj = (const float*)d_in[4];
    float* outp = (float*)d_out;

    cudaFuncSetAttribute(attn_kernel,
                         cudaFuncAttributeMaxDynamicSharedMemorySize, ATTN_SMEM);
    cudaFuncSetAttribute(qkv_mma_kernel,
                         cudaFuncAttributeMaxDynamicSharedMemorySize, GEMM_SMEM);
    cudaFuncSetAttribute(proj_mma_kernel,
                         cudaFuncAttributeMaxDynamicSharedMemorySize, GEMM_SMEM);

    wbake_kernel<<<dim3(64, 4), 256>>>(wq, wk, wv, wproj);
    xsplit_kernel<<<dim3(HW / 32, C / 32, BATCH), 256>>>(x);
    qkv_mma_kernel<<<dim3(NTILES, 3, BATCH), 256, GEMM_SMEM>>>();
    attn_kernel<<<dim3(W / TX, H / TY, HEADS * BATCH), 256, ATTN_SMEM>>>();
    proj_mma_kernel<<<dim3(NTILES, BATCH), 256, GEMM_SMEM>>>(outp);
}